// round 13
// baseline (speedup 1.0000x reference)
#include <cuda_runtime.h>
#include <math.h>

#define N_NODES 50000
#define N_EDGES 800000
#define NUM_RELS 16
#define H_DIM 128
#define LIN_DIM 512

#define CAP1 256
#define CAPE1 512
#define CAPE2 4096

#define BM_WORDS ((N_NODES + 31) / 32)   // 1563

#define NB 148                 // 1 block/SM
#define NT 1024                // 32 warps/SM
#define NQ (N_EDGES / 4)       // 200000 int4 quads
#define QPB ((NQ + NB - 1) / NB)     // 1352 quads per block

#define NSALL  (N_NODES * NUM_RELS)      // 800000 floats
#define NSALL4 (NSALL / 4)               // 200000 float4
#define SPB    ((NSALL4 + NB - 1) / NB)  // 1352 float4 per block

// -------- scratch (device globals; zero-init valid; self-cleaning per launch) --------
__device__ int          g_slot1[N_NODES];       // 0 = absent, slot+1
__device__ unsigned int g_bm1[BM_WORDS + 1];
__device__ int    g_n1, g_ne1, g_ne2;
__device__ int    g_s1_nodes[CAP1];
__device__ int    g_e1_src[CAPE1];
__device__ int    g_e2_src[CAPE2];
__device__ int    g_e2_dslot[CAPE2];
__device__ float2 g_cn[N_NODES];                // {norm, as_float(cls)} packed in P1
__device__ float  g_Sall[NSALL];                // cleared in P1 (per-block slice)
__device__ float  g_h2[CAP1 * H_DIM];           // cleared in P1 (block 1)
__device__ float  g_root[H_DIM];                // cleared in P1 (block 0)

// persistent-generation grid barrier
__device__ unsigned g_bar_cnt;
__device__ unsigned g_bar_gen;

__device__ __forceinline__ unsigned atom_add_release_gpu(unsigned* p, unsigned v) {
    unsigned old;
    asm volatile("atom.add.release.gpu.u32 %0, [%1], %2;"
                 : "=r"(old) : "l"(p), "r"(v) : "memory");
    return old;
}
__device__ __forceinline__ unsigned ld_acquire_gpu(unsigned* p) {
    unsigned v;
    asm volatile("ld.acquire.gpu.u32 %0, [%1];" : "=r"(v) : "l"(p) : "memory");
    return v;
}
__device__ __forceinline__ void st_release_gpu(unsigned* p, unsigned v) {
    asm volatile("st.release.gpu.u32 [%0], %1;" :: "l"(p), "r"(v) : "memory");
}

#define GRID_SYNC()                                                          \
    do {                                                                     \
        __syncthreads();                                                     \
        if (threadIdx.x == 0) {                                              \
            if (atom_add_release_gpu(&g_bar_cnt, 1u) == (unsigned)(NB - 1)) {\
                *(volatile unsigned*)&g_bar_cnt = 0u;                        \
                st_release_gpu(&g_bar_gen, my_gen + 1u);                     \
            } else {                                                         \
                int spin = 0;                                                \
                while (ld_acquire_gpu(&g_bar_gen) == my_gen)                 \
                    if (++spin > 64) __nanosleep(32);                        \
            }                                                                \
            my_gen++;                                                        \
        }                                                                    \
        __syncthreads();                                                     \
    } while (0)

__device__ __forceinline__ float warp_max_f(float v) {
#pragma unroll
    for (int o = 16; o > 0; o >>= 1) v = fmaxf(v, __shfl_down_sync(0xffffffffu, v, o));
    return v;
}
__device__ __forceinline__ float warp_sum_f(float v) {
#pragma unroll
    for (int o = 16; o > 0; o >>= 1) v += __shfl_down_sync(0xffffffffu, v, o);
    return v;
}

__global__ void __launch_bounds__(NT, 1) k_fused(
    const int* __restrict__ cls, const float* __restrict__ norm,
    const int* __restrict__ src, const int* __restrict__ dst,
    const float* __restrict__ W0, const float* __restrict__ W1,
    const float* __restrict__ W2,
    const float* __restrict__ a1_w, const float* __restrict__ a1_b,
    const float* __restrict__ a2_w, const float* __restrict__ a2_b,
    const float* __restrict__ c1_w, const float* __restrict__ c1_b,
    const float* __restrict__ c2_w, const float* __restrict__ c2_b,
    float* __restrict__ out, int out_size)
{
    const int tx  = threadIdx.x;
    const int bid = blockIdx.x;
    const int gt  = bid * NT + tx;
    const int wid  = tx >> 5;
    const int lane = tx & 31;

    const int q0     = bid * QPB;
    const int nq_blk = (NQ - q0 < QPB) ? (NQ - q0) : QPB;

    unsigned my_gen = 0;
    if (tx == 0) my_gen = ld_acquire_gpu(&g_bar_gen);

    __shared__ int4     sh_dst4[QPB + 1];          // 21.6 KB
    __shared__ unsigned sh_bm[BM_WORDS + 1];       // 6.3 KB
    __shared__ float    sh_h[H_DIM];
    __shared__ float    sh_p[NT];                  // 4 KB (heads)
    __shared__ float    s_hid[LIN_DIM];            // 2 KB (heads)
    __shared__ float    s_mx, s_sum;

    // ===== P1: pack cn; clear S_all slice / h2 / root; scan dst==0 -> S1/E1 =====
    {
        if (gt < N_NODES)
            g_cn[gt] = make_float2(norm[gt], __int_as_float(cls[gt]));

        {
            const float4 z4 = make_float4(0.f, 0.f, 0.f, 0.f);
            int s0 = bid * SPB;
            int sn = NSALL4 - s0; if (sn > SPB) sn = SPB;
            for (int i = tx; i < sn; i += NT)
                reinterpret_cast<float4*>(g_Sall)[s0 + i] = z4;
        }
        if (bid == 1) {
            const float4 z4 = make_float4(0.f, 0.f, 0.f, 0.f);
            for (int i = tx; i < (CAP1 * H_DIM) / 4; i += NT)
                reinterpret_cast<float4*>(g_h2)[i] = z4;
        }
        if (bid == 0 && tx < H_DIM) g_root[tx] = 0.f;

#pragma unroll
        for (int half = 0; half < 2; half++) {
            int li = tx + half * NT;
            if (li < nq_blk) {
                int qi = q0 + li;
                const int4 d4 = reinterpret_cast<const int4*>(dst)[qi];
                sh_dst4[li] = d4;
                int dv[4] = {d4.x, d4.y, d4.z, d4.w};
#pragma unroll
                for (int k = 0; k < 4; k++) {
                    if (dv[k] == 0) {
                        int s = src[4 * qi + k];
                        int p = atomicAdd(&g_ne1, 1);
                        if (p < CAPE1) g_e1_src[p] = s;
                        if (atomicCAS(&g_slot1[s], 0, -1) == 0) {
                            int sl = atomicAdd(&g_n1, 1);
                            if (sl < CAP1) g_s1_nodes[sl] = s;
                            g_slot1[s] = sl + 1;
                            atomicOr(&g_bm1[s >> 5], 1u << (s & 31));
                        }
                    }
                }
            }
        }
    }
    GRID_SYNC();   // barrier 1

    // ===== P2: full scan: S_all RED + (dst in S1 -> E2 global list) =====
    {
        for (int i = tx; i <= BM_WORDS; i += NT) sh_bm[i] = g_bm1[i];
        __syncthreads();
#pragma unroll
        for (int half = 0; half < 2; half++) {
            int li = tx + half * NT;
            if (li < nq_blk) {
                int qi = q0 + li;
                const int4 d4 = sh_dst4[li];
                const int4 s4 = reinterpret_cast<const int4*>(src)[qi];
                int dv[4] = {d4.x, d4.y, d4.z, d4.w};
                int sv[4] = {s4.x, s4.y, s4.z, s4.w};
#pragma unroll
                for (int k = 0; k < 4; k++) {
                    int d = dv[k], s = sv[k];
                    float2 cn = g_cn[s];
                    int c = __float_as_int(cn.y);
                    atomicAdd(&g_Sall[d * NUM_RELS + c], cn.x);   // RED, no return
                    if (sh_bm[d >> 5] & (1u << (d & 31))) {
                        int sl = g_slot1[d] - 1;
                        if (sl >= 0 && sl < CAP1) {
                            int p = atomicAdd(&g_ne2, 1);
                            if (p < CAPE2) { g_e2_src[p] = s; g_e2_dslot[p] = sl; }
                        }
                    }
                }
            }
        }
    }
    GRID_SYNC();   // barrier 2

    // ===== P3: one WARP per E2 edge: msg1 = (relu(Sall[s].T0) @ W1[c]) * nm -> h2 =====
    // edge e -> block e % NB, warp e / NB  (<=3 busy warps per block, all parallel)
    {
        int ne2 = *(volatile int*)&g_ne2; if (ne2 > CAPE2) ne2 = CAPE2;
        for (int e = bid + wid * NB; e < ne2; e += NB * 32) {
            int s   = g_e2_src[e];
            int dsl = g_e2_dslot[e];
            if (dsl < 0 || dsl >= CAP1) continue;
            float2 cn = g_cn[s];
            int c = __float_as_int(cn.y);
            float sv = (lane < NUM_RELS) ? g_Sall[s * NUM_RELS + lane] : 0.f;
            float h[4] = {0.f, 0.f, 0.f, 0.f};
#pragma unroll
            for (int r = 0; r < NUM_RELS; r++) {
                float svr = __shfl_sync(0xffffffffu, sv, r);
                const float* T0r = W0 + (r * NUM_RELS + r) * H_DIM + lane;
#pragma unroll
                for (int i = 0; i < 4; i++)
                    h[i] = fmaf(svr, T0r[32 * i], h[i]);
            }
#pragma unroll
            for (int i = 0; i < 4; i++) h[i] = fmaxf(h[i], 0.f);

            const float* Wc = W1 + c * H_DIM * H_DIM;
            float acc[4] = {0.f, 0.f, 0.f, 0.f};
#pragma unroll
            for (int kb = 0; kb < 4; kb++) {
                float hreg = h[kb];
#pragma unroll 8
                for (int l = 0; l < 32; l++) {
                    float hk = __shfl_sync(0xffffffffu, hreg, l);
                    const float* Wr = Wc + (kb * 32 + l) * H_DIM + lane;
#pragma unroll
                    for (int i = 0; i < 4; i++)
                        acc[i] = fmaf(hk, Wr[32 * i], acc[i]);
                }
            }
#pragma unroll
            for (int i = 0; i < 4; i++)
                atomicAdd(&g_h2[dsl * H_DIM + lane + 32 * i], acc[i] * cn.x);
        }
    }
    GRID_SYNC();   // barrier 3

    // ===== P4: one WARP per S1 node: msg2 = (relu(h2) @ W2[c]) * nm; root += mult*msg2 =====
    {
        int n1v = *(volatile int*)&g_n1; if (n1v > CAP1)  n1v = CAP1;
        int ne1 = *(volatile int*)&g_ne1; if (ne1 > CAPE1) ne1 = CAPE1;
        for (int sl = bid + wid * NB; sl < n1v; sl += NB * 32) {
            int node = g_s1_nodes[sl];
            float2 cn = g_cn[node];
            int c = __float_as_int(cn.y);
            float h[4];
#pragma unroll
            for (int i = 0; i < 4; i++)
                h[i] = fmaxf(g_h2[sl * H_DIM + lane + 32 * i], 0.f);

            const float* Wc = W2 + c * H_DIM * H_DIM;
            float acc[4] = {0.f, 0.f, 0.f, 0.f};
#pragma unroll
            for (int kb = 0; kb < 4; kb++) {
                float hreg = h[kb];
#pragma unroll 8
                for (int l = 0; l < 32; l++) {
                    float hk = __shfl_sync(0xffffffffu, hreg, l);
                    const float* Wr = Wc + (kb * 32 + l) * H_DIM + lane;
#pragma unroll
                    for (int i = 0; i < 4; i++)
                        acc[i] = fmaf(hk, Wr[32 * i], acc[i]);
                }
            }
            int mult = 0;
            for (int i = 0; i < ne1; i++) mult += (g_e1_src[i] == node);  // broadcast loads
            if (mult > 0) {
                float fm = cn.x * (float)mult;
#pragma unroll
                for (int i = 0; i < 4; i++)
                    atomicAdd(&g_root[lane + 32 * i], acc[i] * fm);
            }
        }
    }

    // ===== last barrier: arrive (release); only blocks 0..2 wait =====
    __syncthreads();
    if (tx == 0) {
        if (atom_add_release_gpu(&g_bar_cnt, 1u) == (unsigned)(NB - 1)) {
            *(volatile unsigned*)&g_bar_cnt = 0u;
            st_release_gpu(&g_bar_gen, my_gen + 1u);
        } else if (bid < 3) {
            int spin = 0;
            while (ld_acquire_gpu(&g_bar_gen) == my_gen)
                if (++spin > 64) __nanosleep(32);
        }
        my_gen++;
    }
    __syncthreads();
    if (bid >= 3) return;

    // ===== epilogue: block 2 cleans S1 state; blocks 0/1 do heads =====
    if (bid == 2) {
        int n1v = g_n1; if (n1v > CAP1) n1v = CAP1;
        for (int i = tx; i < n1v; i += NT) {
            int s = g_s1_nodes[i];
            g_slot1[s] = 0;
            g_bm1[s >> 5] = 0u;
        }
        __syncthreads();
        if (tx == 0) { g_n1 = 0; g_ne1 = 0; g_ne2 = 0; }
        return;
    }

    // blocks 0 (actor) and 1 (critic): softmax(root) locally, then head
    {
        const int t = tx;
        if (t < H_DIM) sh_h[t] = g_root[t];
        __syncthreads();
        if (wid == 0) {
            float m = fmaxf(fmaxf(sh_h[lane], sh_h[lane + 32]),
                            fmaxf(sh_h[lane + 64], sh_h[lane + 96]));
            m = warp_max_f(m);
            if (lane == 0) s_mx = m;
        }
        __syncthreads();
        if (t < H_DIM) sh_h[t] = expf(sh_h[t] - s_mx);
        __syncthreads();
        if (wid == 0) {
            float sm = sh_h[lane] + sh_h[lane + 32] + sh_h[lane + 64] + sh_h[lane + 96];
            sm = warp_sum_f(sm);
            if (lane == 0) s_sum = sm;
        }
        __syncthreads();
        if (t < H_DIM) sh_h[t] *= (1.f / s_sum);
        __syncthreads();

        if (bid == 0) {
            if (t < LIN_DIM) {
                float a = a1_b[t];
#pragma unroll 8
                for (int k = 0; k < H_DIM; k++) a = fmaf(sh_h[k], a1_w[k * LIN_DIM + t], a);
                s_hid[t] = fmaxf(a, 0.f);
            }
            __syncthreads();
            if (t < LIN_DIM) {
                int q = t >> 7, j = t & 127;
                const int k0 = q * 128;
                float p = 0.f;
#pragma unroll 8
                for (int k = 0; k < 128; k++)
                    p = fmaf(s_hid[k0 + k], a2_w[(k0 + k) * H_DIM + j], p);
                sh_p[t] = p;
            }
            __syncthreads();
            if (t < H_DIM)
                out[t] = a2_b[t] + sh_p[t] + sh_p[t + 128] + sh_p[t + 256] + sh_p[t + 384];
        } else {
            if (t < LIN_DIM) {
                float a = c1_b[t];
#pragma unroll 8
                for (int k = 0; k < H_DIM; k++) a = fmaf(sh_h[k], c1_w[k * LIN_DIM + t], a);
                s_hid[t] = fmaxf(a, 0.f);
            }
            __syncthreads();
            if (t < LIN_DIM) {
                float p = warp_sum_f(s_hid[t] * c2_w[t]);
                if (lane == 0) sh_p[wid] = p;
            }
            __syncthreads();
            if (t == 0) {
                float a = c2_b[0];
#pragma unroll
                for (int i = 0; i < 16; i++) a += sh_p[i];
                if (out_size > H_DIM) out[H_DIM] = a;
            }
        }
    }
}

// ---------------- launch ----------------
extern "C" void kernel_launch(void* const* d_in, const int* in_sizes, int n_in,
                              void* d_out, int out_size) {
    const int*   cls  = (const int*)  d_in[0];
    const float* norm = (const float*)d_in[1];
    const int*   src  = (const int*)  d_in[2];
    const int*   dst  = (const int*)  d_in[3];
    const float* W0   = (const float*)d_in[4];
    const float* W1   = (const float*)d_in[5];
    const float* W2   = (const float*)d_in[6];
    const float* a1_w = (const float*)d_in[7];
    const float* a1_b = (const float*)d_in[8];
    const float* a2_w = (const float*)d_in[9];
    const float* a2_b = (const float*)d_in[10];
    const float* c1_w = (const float*)d_in[11];
    const float* c1_b = (const float*)d_in[12];
    const float* c2_w = (const float*)d_in[13];
    const float* c2_b = (const float*)d_in[14];
    float* out = (float*)d_out;

    k_fused<<<NB, NT>>>(cls, norm, src, dst, W0, W1, W2,
                        a1_w, a1_b, a2_w, a2_b, c1_w, c1_b, c2_w, c2_b,
                        out, out_size);
}

// round 14
// speedup vs baseline: 1.2721x; 1.2721x over previous
#include <cuda_runtime.h>
#include <math.h>

#define N_NODES 50000
#define N_EDGES 800000
#define NUM_RELS 16
#define H_DIM 128
#define LIN_DIM 512

#define CAP1 256
#define CAPE1 512
#define CAPE2 4096

#define BM_WORDS ((N_NODES + 31) / 32)   // 1563

#define NB 148                 // 1 block/SM
#define NT 1024                // 32 warps/SM
#define NQ (N_EDGES / 4)       // 200000 int4 quads
#define QPB ((NQ + NB - 1) / NB)     // 1352 quads per block
#define GRP (NT / H_DIM)       // 8 k-groups (P4 GEMV)
#define KS  (H_DIM / GRP)      // 16 k's per group
#define GRP2 4                 // 4 k-groups (P3 half-block GEMV, 512 thr)
#define KS2  (H_DIM / GRP2)    // 32 k's per group

#define NSALL  (N_NODES * NUM_RELS)      // 800000 floats
#define NSALL4 (NSALL / 4)               // 200000 float4
#define SPB    ((NSALL4 + NB - 1) / NB)  // 1352 float4 per block

// -------- scratch (device globals; zero-init valid; self-cleaning per launch) --------
__device__ int          g_slot1[N_NODES];       // 0 = absent, slot+1
__device__ unsigned int g_bm1[BM_WORDS + 1];
__device__ int    g_n1, g_ne1, g_ne2;
__device__ int    g_s1_nodes[CAP1];
__device__ int    g_e1_src[CAPE1];
__device__ int    g_e2_src[CAPE2];
__device__ int    g_e2_dslot[CAPE2];
__device__ float2 g_cn[N_NODES];                // {norm, as_float(cls)} packed in P1
__device__ float  g_Sall[NSALL];                // cleared in P1 (per-block slice)
__device__ float  g_h2[CAP1 * H_DIM];           // cleared in P1 (block 1)
__device__ float  g_root[H_DIM];                // cleared in P1 (block 0)

// persistent-generation grid barrier
__device__ unsigned g_bar_cnt;
__device__ unsigned g_bar_gen;

__device__ __forceinline__ unsigned atom_add_release_gpu(unsigned* p, unsigned v) {
    unsigned old;
    asm volatile("atom.add.release.gpu.u32 %0, [%1], %2;"
                 : "=r"(old) : "l"(p), "r"(v) : "memory");
    return old;
}
__device__ __forceinline__ unsigned ld_acquire_gpu(unsigned* p) {
    unsigned v;
    asm volatile("ld.acquire.gpu.u32 %0, [%1];" : "=r"(v) : "l"(p) : "memory");
    return v;
}
__device__ __forceinline__ void st_release_gpu(unsigned* p, unsigned v) {
    asm volatile("st.release.gpu.u32 [%0], %1;" :: "l"(p), "r"(v) : "memory");
}

#define GRID_SYNC()                                                          \
    do {                                                                     \
        __syncthreads();                                                     \
        if (threadIdx.x == 0) {                                              \
            if (atom_add_release_gpu(&g_bar_cnt, 1u) == (unsigned)(NB - 1)) {\
                *(volatile unsigned*)&g_bar_cnt = 0u;                        \
                st_release_gpu(&g_bar_gen, my_gen + 1u);                     \
            } else {                                                         \
                int spin = 0;                                                \
                while (ld_acquire_gpu(&g_bar_gen) == my_gen)                 \
                    if (++spin > 64) __nanosleep(32);                        \
            }                                                                \
            my_gen++;                                                        \
        }                                                                    \
        __syncthreads();                                                     \
    } while (0)

__device__ __forceinline__ float warp_max_f(float v) {
#pragma unroll
    for (int o = 16; o > 0; o >>= 1) v = fmaxf(v, __shfl_down_sync(0xffffffffu, v, o));
    return v;
}
__device__ __forceinline__ float warp_sum_f(float v) {
#pragma unroll
    for (int o = 16; o > 0; o >>= 1) v += __shfl_down_sync(0xffffffffu, v, o);
    return v;
}

__global__ void __launch_bounds__(NT, 1) k_fused(
    const int* __restrict__ cls, const float* __restrict__ norm,
    const int* __restrict__ src, const int* __restrict__ dst,
    const float* __restrict__ W0, const float* __restrict__ W1,
    const float* __restrict__ W2,
    const float* __restrict__ a1_w, const float* __restrict__ a1_b,
    const float* __restrict__ a2_w, const float* __restrict__ a2_b,
    const float* __restrict__ c1_w, const float* __restrict__ c1_b,
    const float* __restrict__ c2_w, const float* __restrict__ c2_b,
    float* __restrict__ out, int out_size)
{
    const int tx  = threadIdx.x;
    const int bid = blockIdx.x;
    const int gt  = bid * NT + tx;
    const int wid  = tx >> 5;
    const int lane = tx & 31;

    const int q0     = bid * QPB;
    const int nq_blk = (NQ - q0 < QPB) ? (NQ - q0) : QPB;

    unsigned my_gen = 0;
    if (tx == 0) my_gen = ld_acquire_gpu(&g_bar_gen);

    __shared__ int4     sh_dst4[QPB + 1];          // 21.6 KB
    __shared__ int4     sh_src4[QPB + 1];          // 21.6 KB
    __shared__ unsigned sh_bm[BM_WORDS + 1];       // 6.3 KB
    __shared__ float    sh_hh[2][H_DIM];           // P3 half-block h
    __shared__ float    sh_h[H_DIM];
    __shared__ float    sh_p[NT];                  // 4 KB
    __shared__ float    s_hid[LIN_DIM];            // 2 KB
    __shared__ float    s_mx, s_sum;

    // ===== P1: pack cn; clear S_all slice / h2 / root; cache dst+src; scan dst==0 =====
    {
        if (gt < N_NODES)
            g_cn[gt] = make_float2(norm[gt], __int_as_float(cls[gt]));

        {
            const float4 z4 = make_float4(0.f, 0.f, 0.f, 0.f);
            int s0 = bid * SPB;
            int sn = NSALL4 - s0; if (sn > SPB) sn = SPB;
            for (int i = tx; i < sn; i += NT)
                reinterpret_cast<float4*>(g_Sall)[s0 + i] = z4;
        }
        if (bid == 1) {
            const float4 z4 = make_float4(0.f, 0.f, 0.f, 0.f);
            for (int i = tx; i < (CAP1 * H_DIM) / 4; i += NT)
                reinterpret_cast<float4*>(g_h2)[i] = z4;
        }
        if (bid == 0 && tx < H_DIM) g_root[tx] = 0.f;

#pragma unroll
        for (int half = 0; half < 2; half++) {
            int li = tx + half * NT;
            if (li < nq_blk) {
                int qi = q0 + li;
                const int4 d4 = reinterpret_cast<const int4*>(dst)[qi];
                const int4 s4 = reinterpret_cast<const int4*>(src)[qi];
                sh_dst4[li] = d4;
                sh_src4[li] = s4;
                int dv[4] = {d4.x, d4.y, d4.z, d4.w};
                int sv[4] = {s4.x, s4.y, s4.z, s4.w};
#pragma unroll
                for (int k = 0; k < 4; k++) {
                    if (dv[k] == 0) {
                        int s = sv[k];
                        int p = atomicAdd(&g_ne1, 1);
                        if (p < CAPE1) g_e1_src[p] = s;
                        if (atomicCAS(&g_slot1[s], 0, -1) == 0) {
                            int sl = atomicAdd(&g_n1, 1);
                            if (sl < CAP1) g_s1_nodes[sl] = s;
                            g_slot1[s] = sl + 1;
                            atomicOr(&g_bm1[s >> 5], 1u << (s & 31));
                        }
                    }
                }
            }
        }
    }
    GRID_SYNC();   // barrier 1

    // ===== P2: SMEM re-scan: S_all RED + (dst in S1 -> E2 global list) =====
    {
        for (int i = tx; i <= BM_WORDS; i += NT) sh_bm[i] = g_bm1[i];
        __syncthreads();
#pragma unroll
        for (int half = 0; half < 2; half++) {
            int li = tx + half * NT;
            if (li < nq_blk) {
                const int4 d4 = sh_dst4[li];
                const int4 s4 = sh_src4[li];
                int dv[4] = {d4.x, d4.y, d4.z, d4.w};
                int sv[4] = {s4.x, s4.y, s4.z, s4.w};
#pragma unroll
                for (int k = 0; k < 4; k++) {
                    int d = dv[k], s = sv[k];
                    float2 cn = g_cn[s];
                    int c = __float_as_int(cn.y);
                    atomicAdd(&g_Sall[d * NUM_RELS + c], cn.x);   // RED, no return
                    if (sh_bm[d >> 5] & (1u << (d & 31))) {
                        int sl = g_slot1[d] - 1;
                        if (sl >= 0 && sl < CAP1) {
                            int p = atomicAdd(&g_ne2, 1);
                            if (p < CAPE2) { g_e2_src[p] = s; g_e2_dslot[p] = sl; }
                        }
                    }
                }
            }
        }
    }
    GRID_SYNC();   // barrier 2

    // ===== P3: two half-block (512-thr) GEMVs per block, one E2 edge each =====
    // msg1 = (relu(S_all[s] . T0) @ W1[c]) * nm  -> h2[dslot] (atomics)
    {
        int ne2 = *(volatile int*)&g_ne2; if (ne2 > CAPE2) ne2 = CAPE2;
        const int grp = tx >> 9;              // 0 or 1
        const int gtx = tx & 511;
        const int j = gtx & (H_DIM - 1), q = gtx >> 7;   // q in 0..3
        const int trips = (ne2 + 2 * NB - 1) / (2 * NB);
        for (int t = 0; t < trips; t++) {
            int e = t * 2 * NB + bid * 2 + grp;
            bool act = (e < ne2);
            int s = 0, dsl = -1;
            float2 cn = make_float2(0.f, 0.f);
            if (act) {
                s   = g_e2_src[e];
                dsl = g_e2_dslot[e];
                cn  = g_cn[s];
                if (gtx < H_DIM) {
                    const float* Sv = &g_Sall[s * NUM_RELS];
                    float h = 0.f;
#pragma unroll
                    for (int r = 0; r < NUM_RELS; r++)
                        h = fmaf(Sv[r], W0[(r * NUM_RELS + r) * H_DIM + gtx], h);
                    sh_hh[grp][gtx] = fmaxf(h, 0.f);
                }
            }
            __syncthreads();
            if (act) {
                int c = __float_as_int(cn.y);
                const float* Wc = W1 + c * H_DIM * H_DIM;
                float p = 0.f;
#pragma unroll
                for (int kk = 0; kk < KS2; kk++) {
                    int k = q * KS2 + kk;
                    p = fmaf(sh_hh[grp][k], Wc[k * H_DIM + j], p);
                }
                sh_p[tx] = p;
            }
            __syncthreads();
            if (act && gtx < H_DIM && dsl >= 0 && dsl < CAP1) {
                float a = 0.f;
#pragma unroll
                for (int g = 0; g < GRP2; g++) a += sh_p[grp * 512 + gtx + g * H_DIM];
                atomicAdd(&g_h2[dsl * H_DIM + gtx], a * cn.x);
            }
            __syncthreads();
        }
    }
    GRID_SYNC();   // barrier 3

    // ===== P4: block-wide msg2 per S1 node + root accumulation =====
    {
        int n1v = *(volatile int*)&g_n1; if (n1v > CAP1)  n1v = CAP1;
        int ne1 = *(volatile int*)&g_ne1; if (ne1 > CAPE1) ne1 = CAPE1;
        if (bid < n1v) {
            const int j = tx & (H_DIM - 1), q = tx >> 7;
            for (int sl = bid; sl < n1v; sl += NB) {
                if (tx < H_DIM) sh_h[tx] = fmaxf(g_h2[sl * H_DIM + tx], 0.f);
                __syncthreads();
                int node = g_s1_nodes[sl];
                float2 cn = g_cn[node];
                int c = __float_as_int(cn.y);
                const float* Wc = W2 + c * H_DIM * H_DIM;
                float p = 0.f;
#pragma unroll
                for (int kk = 0; kk < KS; kk++) {
                    int k = q * KS + kk;
                    p = fmaf(sh_h[k], Wc[k * H_DIM + j], p);
                }
                sh_p[tx] = p;
                __syncthreads();
                if (tx < H_DIM) {
                    float a = 0.f;
#pragma unroll
                    for (int g = 0; g < GRP; g++) a += sh_p[tx + g * H_DIM];
                    a *= cn.x;
                    int mult = 0;
                    for (int i = 0; i < ne1; i++) mult += (g_e1_src[i] == node);
                    if (mult > 0) atomicAdd(&g_root[tx], a * (float)mult);
                }
                __syncthreads();
            }
        }
    }

    // ===== last barrier: arrive (release); only blocks 0..2 wait =====
    __syncthreads();
    if (tx == 0) {
        if (atom_add_release_gpu(&g_bar_cnt, 1u) == (unsigned)(NB - 1)) {
            *(volatile unsigned*)&g_bar_cnt = 0u;
            st_release_gpu(&g_bar_gen, my_gen + 1u);
        } else if (bid < 3) {
            int spin = 0;
            while (ld_acquire_gpu(&g_bar_gen) == my_gen)
                if (++spin > 64) __nanosleep(32);
        }
        my_gen++;
    }
    __syncthreads();
    if (bid >= 3) return;

    // ===== epilogue: block 2 cleans S1 state; blocks 0/1 do heads =====
    if (bid == 2) {
        int n1v = g_n1; if (n1v > CAP1) n1v = CAP1;
        for (int i = tx; i < n1v; i += NT) {
            int s = g_s1_nodes[i];
            g_slot1[s] = 0;
            g_bm1[s >> 5] = 0u;
        }
        __syncthreads();
        if (tx == 0) { g_n1 = 0; g_ne1 = 0; g_ne2 = 0; }
        return;
    }

    // blocks 0 (actor) and 1 (critic): softmax(root) locally, then head
    {
        const int t = tx;
        if (t < H_DIM) sh_h[t] = g_root[t];
        __syncthreads();
        if (wid == 0) {
            float m = fmaxf(fmaxf(sh_h[lane], sh_h[lane + 32]),
                            fmaxf(sh_h[lane + 64], sh_h[lane + 96]));
            m = warp_max_f(m);
            if (lane == 0) s_mx = m;
        }
        __syncthreads();
        if (t < H_DIM) sh_h[t] = expf(sh_h[t] - s_mx);
        __syncthreads();
        if (wid == 0) {
            float sm = sh_h[lane] + sh_h[lane + 32] + sh_h[lane + 64] + sh_h[lane + 96];
            sm = warp_sum_f(sm);
            if (lane == 0) s_sum = sm;
        }
        __syncthreads();
        if (t < H_DIM) sh_h[t] *= (1.f / s_sum);
        __syncthreads();

        if (bid == 0) {
            if (t < LIN_DIM) {
                float a = a1_b[t];
#pragma unroll 8
                for (int k = 0; k < H_DIM; k++) a = fmaf(sh_h[k], a1_w[k * LIN_DIM + t], a);
                s_hid[t] = fmaxf(a, 0.f);
            }
            __syncthreads();
            if (t < LIN_DIM) {
                int q = t >> 7, j = t & 127;
                const int k0 = q * 128;
                float p = 0.f;
#pragma unroll 8
                for (int k = 0; k < 128; k++)
                    p = fmaf(s_hid[k0 + k], a2_w[(k0 + k) * H_DIM + j], p);
                sh_p[t] = p;
            }
            __syncthreads();
            if (t < H_DIM)
                out[t] = a2_b[t] + sh_p[t] + sh_p[t + 128] + sh_p[t + 256] + sh_p[t + 384];
        } else {
            if (t < LIN_DIM) {
                float a = c1_b[t];
#pragma unroll 8
                for (int k = 0; k < H_DIM; k++) a = fmaf(sh_h[k], c1_w[k * LIN_DIM + t], a);
                s_hid[t] = fmaxf(a, 0.f);
            }
            __syncthreads();
            if (t < LIN_DIM) {
                float p = warp_sum_f(s_hid[t] * c2_w[t]);
                if (lane == 0) sh_p[wid] = p;
            }
            __syncthreads();
            if (t == 0) {
                float a = c2_b[0];
#pragma unroll
                for (int i = 0; i < 16; i++) a += sh_p[i];
                if (out_size > H_DIM) out[H_DIM] = a;
            }
        }
    }
}

// ---------------- launch ----------------
extern "C" void kernel_launch(void* const* d_in, const int* in_sizes, int n_in,
                              void* d_out, int out_size) {
    const int*   cls  = (const int*)  d_in[0];
    const float* norm = (const float*)d_in[1];
    const int*   src  = (const int*)  d_in[2];
    const int*   dst  = (const int*)  d_in[3];
    const float* W0   = (const float*)d_in[4];
    const float* W1   = (const float*)d_in[5];
    const float* W2   = (const float*)d_in[6];
    const float* a1_w = (const float*)d_in[7];
    const float* a1_b = (const float*)d_in[8];
    const float* a2_w = (const float*)d_in[9];
    const float* a2_b = (const float*)d_in[10];
    const float* c1_w = (const float*)d_in[11];
    const float* c1_b = (const float*)d_in[12];
    const float* c2_w = (const float*)d_in[13];
    const float* c2_b = (const float*)d_in[14];
    float* out = (float*)d_out;

    k_fused<<<NB, NT>>>(cls, norm, src, dst, W0, W1, W2,
                        a1_w, a1_b, a2_w, a2_b, c1_w, c1_b, c2_w, c2_b,
                        out, out_size);
}

// round 15
// speedup vs baseline: 1.2941x; 1.0173x over previous
#include <cuda_runtime.h>
#include <math.h>
#include <stdint.h>

#define N_NODES 50000
#define N_EDGES 800000
#define NUM_RELS 16
#define H_DIM 128
#define LIN_DIM 512

#define CAP1 256
#define CAPE1 512
#define CAPE2 4096

#define BM_WORDS ((N_NODES + 31) / 32)   // 1563

#define NB 148                 // 1 block/SM
#define NT 1024                // 32 warps/SM
#define NQ (N_EDGES / 4)       // 200000 int4 quads
#define QPB ((NQ + NB - 1) / NB)     // 1352 quads per block
#define GRP (NT / H_DIM)       // 8 k-groups (P4 GEMV)
#define KS  (H_DIM / GRP)      // 16 k's per group
#define GRP2 4                 // 4 k-groups (P3 half-block GEMV, 512 thr)
#define KS2  (H_DIM / GRP2)    // 32 k's per group

#define NSALL  (N_NODES * NUM_RELS)      // 800000 floats
#define NSALL4 (NSALL / 4)               // 200000 float4
#define SPB    ((NSALL4 + NB - 1) / NB)  // 1352 float4 per block

// -------- scratch (device globals; zero-init valid; self-cleaning per launch) --------
__device__ int          g_slot1[N_NODES];       // 0 = absent, slot+1
__device__ unsigned int g_bm1[BM_WORDS + 1];
__device__ int    g_n1, g_ne1, g_ne2;
__device__ int    g_s1_nodes[CAP1];
__device__ int    g_e1_src[CAPE1];
__device__ int    g_e2_src[CAPE2];
__device__ int    g_e2_dslot[CAPE2];
__device__ float2 g_cn[N_NODES];                // {norm, as_float(cls)} packed in P1
__device__ float  g_Sall[NSALL];                // cleared in P1 (per-block slice)
__device__ float  g_h2[CAP1 * H_DIM];           // cleared in P1 (block 1)
__device__ float  g_root[H_DIM];                // cleared in P1 (block 0)

// persistent-generation grid barrier
__device__ unsigned g_bar_cnt;
__device__ unsigned g_bar_gen;

__device__ __forceinline__ unsigned atom_add_release_gpu(unsigned* p, unsigned v) {
    unsigned old;
    asm volatile("atom.add.release.gpu.u32 %0, [%1], %2;"
                 : "=r"(old) : "l"(p), "r"(v) : "memory");
    return old;
}
__device__ __forceinline__ unsigned ld_acquire_gpu(unsigned* p) {
    unsigned v;
    asm volatile("ld.acquire.gpu.u32 %0, [%1];" : "=r"(v) : "l"(p) : "memory");
    return v;
}
__device__ __forceinline__ void st_release_gpu(unsigned* p, unsigned v) {
    asm volatile("st.release.gpu.u32 [%0], %1;" :: "l"(p), "r"(v) : "memory");
}

// ---- bulk-async copy helpers (sm_90+; UBLKCP on sm_103a) ----
__device__ __forceinline__ uint32_t smem_u32(const void* p) {
    uint32_t a;
    asm("{ .reg .u64 t; cvta.to.shared.u64 t, %1; cvt.u32.u64 %0, t; }"
        : "=r"(a) : "l"(p));
    return a;
}
__device__ __forceinline__ void mbar_init(uint32_t mb, uint32_t cnt) {
    asm volatile("mbarrier.init.shared.b64 [%0], %1;" :: "r"(mb), "r"(cnt) : "memory");
}
__device__ __forceinline__ void mbar_expect_tx(uint32_t mb, uint32_t bytes) {
    asm volatile("mbarrier.arrive.expect_tx.shared.b64 _, [%0], %1;"
                 :: "r"(mb), "r"(bytes) : "memory");
}
__device__ __forceinline__ void bulk_g2s(uint32_t smem, const void* gsrc,
                                         uint32_t bytes, uint32_t mb) {
    asm volatile("cp.async.bulk.shared::cta.global.mbarrier::complete_tx::bytes "
                 "[%0], [%1], %2, [%3];"
                 :: "r"(smem), "l"(gsrc), "r"(bytes), "r"(mb) : "memory");
}
__device__ __forceinline__ void mbar_wait0(uint32_t mb) {
    uint32_t done;
    asm volatile(
        "{\n\t.reg .pred p;\n\t"
        "mbarrier.try_wait.parity.acquire.cta.shared::cta.b64 p, [%1], 0;\n\t"
        "selp.b32 %0, 1, 0, p;\n\t}"
        : "=r"(done) : "r"(mb) : "memory");
    if (!done) {
        asm volatile(
            "{\n\t.reg .pred P1;\n\t"
            "WL_%=:\n\t"
            "mbarrier.try_wait.parity.acquire.cta.shared::cta.b64 P1, [%0], 0, 0x989680;\n\t"
            "@P1 bra.uni WD_%=;\n\t"
            "bra.uni WL_%=;\n\t"
            "WD_%=:\n\t}"
            :: "r"(mb) : "memory");
    }
}

#define GRID_SYNC()                                                          \
    do {                                                                     \
        __syncthreads();                                                     \
        if (threadIdx.x == 0) {                                              \
            if (atom_add_release_gpu(&g_bar_cnt, 1u) == (unsigned)(NB - 1)) {\
                *(volatile unsigned*)&g_bar_cnt = 0u;                        \
                st_release_gpu(&g_bar_gen, my_gen + 1u);                     \
            } else {                                                         \
                int spin = 0;                                                \
                while (ld_acquire_gpu(&g_bar_gen) == my_gen)                 \
                    if (++spin > 64) __nanosleep(32);                        \
            }                                                                \
            my_gen++;                                                        \
        }                                                                    \
        __syncthreads();                                                     \
    } while (0)

__device__ __forceinline__ float warp_max_f(float v) {
#pragma unroll
    for (int o = 16; o > 0; o >>= 1) v = fmaxf(v, __shfl_down_sync(0xffffffffu, v, o));
    return v;
}
__device__ __forceinline__ float warp_sum_f(float v) {
#pragma unroll
    for (int o = 16; o > 0; o >>= 1) v += __shfl_down_sync(0xffffffffu, v, o);
    return v;
}

__global__ void __launch_bounds__(NT, 1) k_fused(
    const int* __restrict__ cls, const float* __restrict__ norm,
    const int* __restrict__ src, const int* __restrict__ dst,
    const float* __restrict__ W0, const float* __restrict__ W1,
    const float* __restrict__ W2,
    const float* __restrict__ a1_w, const float* __restrict__ a1_b,
    const float* __restrict__ a2_w, const float* __restrict__ a2_b,
    const float* __restrict__ c1_w, const float* __restrict__ c1_b,
    const float* __restrict__ c2_w, const float* __restrict__ c2_b,
    float* __restrict__ out, int out_size)
{
    const int tx  = threadIdx.x;
    const int bid = blockIdx.x;
    const int gt  = bid * NT + tx;
    const int wid  = tx >> 5;
    const int lane = tx & 31;

    const int q0     = bid * QPB;
    const int nq_blk = (NQ - q0 < QPB) ? (NQ - q0) : QPB;

    unsigned my_gen = 0;
    if (tx == 0) my_gen = ld_acquire_gpu(&g_bar_gen);

    __shared__ int4     sh_dst4[QPB + 1];          // 21.6 KB (TMA dest)
    __shared__ int4     sh_src4[QPB + 1];          // 21.6 KB (TMA dest)
    __shared__ unsigned sh_bm[BM_WORDS + 1];       // 6.3 KB
    __shared__ float    sh_hh[2][H_DIM];           // P3 half-block h
    __shared__ float    sh_h[H_DIM];
    __shared__ float    sh_p[NT];                  // 4 KB
    __shared__ float    s_hid[LIN_DIM];            // 2 KB
    __shared__ float    s_mx, s_sum;
    __shared__ uint64_t s_mbar;

    const uint32_t mb = smem_u32(&s_mbar);

    // ===== P1: bulk-copy slice -> SMEM (overlapped with pack/clear); scan dst==0 =====
    {
        if (tx == 0) mbar_init(mb, 1);
        __syncthreads();
        if (tx == 0) {
            uint32_t bytes = (uint32_t)nq_blk * 16u;
            mbar_expect_tx(mb, 2u * bytes);
            bulk_g2s(smem_u32(sh_dst4), dst + 4 * q0, bytes, mb);
            bulk_g2s(smem_u32(sh_src4), src + 4 * q0, bytes, mb);
        }

        // overlap: pack cn, clear S_all slice / h2 / root (independent of the copy)
        if (gt < N_NODES)
            g_cn[gt] = make_float2(norm[gt], __int_as_float(cls[gt]));
        {
            const float4 z4 = make_float4(0.f, 0.f, 0.f, 0.f);
            int s0 = bid * SPB;
            int sn = NSALL4 - s0; if (sn > SPB) sn = SPB;
            for (int i = tx; i < sn; i += NT)
                reinterpret_cast<float4*>(g_Sall)[s0 + i] = z4;
        }
        if (bid == 1) {
            const float4 z4 = make_float4(0.f, 0.f, 0.f, 0.f);
            for (int i = tx; i < (CAP1 * H_DIM) / 4; i += NT)
                reinterpret_cast<float4*>(g_h2)[i] = z4;
        }
        if (bid == 0 && tx < H_DIM) g_root[tx] = 0.f;

        mbar_wait0(mb);   // slice resident in SMEM

        // scan from SMEM: dst==0 -> E1 / S1
#pragma unroll
        for (int half = 0; half < 2; half++) {
            int li = tx + half * NT;
            if (li < nq_blk) {
                const int4 d4 = sh_dst4[li];
                int dv[4] = {d4.x, d4.y, d4.z, d4.w};
#pragma unroll
                for (int k = 0; k < 4; k++) {
                    if (dv[k] == 0) {
                        const int* sp = reinterpret_cast<const int*>(&sh_src4[li]);
                        int s = sp[k];
                        int p = atomicAdd(&g_ne1, 1);
                        if (p < CAPE1) g_e1_src[p] = s;
                        if (atomicCAS(&g_slot1[s], 0, -1) == 0) {
                            int sl = atomicAdd(&g_n1, 1);
                            if (sl < CAP1) g_s1_nodes[sl] = s;
                            g_slot1[s] = sl + 1;
                            atomicOr(&g_bm1[s >> 5], 1u << (s & 31));
                        }
                    }
                }
            }
        }
    }
    GRID_SYNC();   // barrier 1

    // ===== P2: SMEM re-scan: batched cn loads -> S_all RED + (dst in S1 -> E2) =====
    {
        for (int i = tx; i <= BM_WORDS; i += NT) sh_bm[i] = g_bm1[i];
        __syncthreads();
#pragma unroll
        for (int half = 0; half < 2; half++) {
            int li = tx + half * NT;
            if (li < nq_blk) {
                const int4 d4 = sh_dst4[li];
                const int4 s4 = sh_src4[li];
                int dv[4] = {d4.x, d4.y, d4.z, d4.w};
                int sv[4] = {s4.x, s4.y, s4.z, s4.w};
                // batch the 4 random cn loads (MLP=4) before any dependent RED
                float2 cnv[4];
#pragma unroll
                for (int k = 0; k < 4; k++) cnv[k] = g_cn[sv[k]];
#pragma unroll
                for (int k = 0; k < 4; k++) {
                    int d = dv[k];
                    int c = __float_as_int(cnv[k].y);
                    atomicAdd(&g_Sall[d * NUM_RELS + c], cnv[k].x);   // RED, no return
                    if (sh_bm[d >> 5] & (1u << (d & 31))) {
                        int sl = g_slot1[d] - 1;
                        if (sl >= 0 && sl < CAP1) {
                            int p = atomicAdd(&g_ne2, 1);
                            if (p < CAPE2) { g_e2_src[p] = sv[k]; g_e2_dslot[p] = sl; }
                        }
                    }
                }
            }
        }
    }
    GRID_SYNC();   // barrier 2

    // ===== P3: two half-block (512-thr) GEMVs per block, one E2 edge each =====
    // msg1 = (relu(S_all[s] . T0) @ W1[c]) * nm  -> h2[dslot] (atomics)
    {
        int ne2 = *(volatile int*)&g_ne2; if (ne2 > CAPE2) ne2 = CAPE2;
        const int grp = tx >> 9;              // 0 or 1
        const int gtx = tx & 511;
        const int j = gtx & (H_DIM - 1), q = gtx >> 7;   // q in 0..3
        const int trips = (ne2 + 2 * NB - 1) / (2 * NB);
        for (int t = 0; t < trips; t++) {
            int e = t * 2 * NB + bid * 2 + grp;
            bool act = (e < ne2);
            int s = 0, dsl = -1;
            float2 cn = make_float2(0.f, 0.f);
            if (act) {
                s   = g_e2_src[e];
                dsl = g_e2_dslot[e];
                cn  = g_cn[s];
                if (gtx < H_DIM) {
                    const float* Sv = &g_Sall[s * NUM_RELS];
                    float h = 0.f;
#pragma unroll
                    for (int r = 0; r < NUM_RELS; r++)
                        h = fmaf(Sv[r], W0[(r * NUM_RELS + r) * H_DIM + gtx], h);
                    sh_hh[grp][gtx] = fmaxf(h, 0.f);
                }
            }
            __syncthreads();
            if (act) {
                int c = __float_as_int(cn.y);
                const float* Wc = W1 + c * H_DIM * H_DIM;
                float p = 0.f;
#pragma unroll
                for (int kk = 0; kk < KS2; kk++) {
                    int k = q * KS2 + kk;
                    p = fmaf(sh_hh[grp][k], Wc[k * H_DIM + j], p);
                }
                sh_p[tx] = p;
            }
            __syncthreads();
            if (act && gtx < H_DIM && dsl >= 0 && dsl < CAP1) {
                float a = 0.f;
#pragma unroll
                for (int g = 0; g < GRP2; g++) a += sh_p[grp * 512 + gtx + g * H_DIM];
                atomicAdd(&g_h2[dsl * H_DIM + gtx], a * cn.x);
            }
            __syncthreads();
        }
    }
    GRID_SYNC();   // barrier 3

    // ===== P4: block-wide msg2 per S1 node + root accumulation =====
    {
        int n1v = *(volatile int*)&g_n1; if (n1v > CAP1)  n1v = CAP1;
        int ne1 = *(volatile int*)&g_ne1; if (ne1 > CAPE1) ne1 = CAPE1;
        if (bid < n1v) {
            const int j = tx & (H_DIM - 1), q = tx >> 7;
            for (int sl = bid; sl < n1v; sl += NB) {
                if (tx < H_DIM) sh_h[tx] = fmaxf(g_h2[sl * H_DIM + tx], 0.f);
                __syncthreads();
                int node = g_s1_nodes[sl];
                float2 cn = g_cn[node];
                int c = __float_as_int(cn.y);
                const float* Wc = W2 + c * H_DIM * H_DIM;
                float p = 0.f;
#pragma unroll
                for (int kk = 0; kk < KS; kk++) {
                    int k = q * KS + kk;
                    p = fmaf(sh_h[k], Wc[k * H_DIM + j], p);
                }
                sh_p[tx] = p;
                __syncthreads();
                if (tx < H_DIM) {
                    float a = 0.f;
#pragma unroll
                    for (int g = 0; g < GRP; g++) a += sh_p[tx + g * H_DIM];
                    a *= cn.x;
                    int mult = 0;
                    for (int i = 0; i < ne1; i++) mult += (g_e1_src[i] == node);
                    if (mult > 0) atomicAdd(&g_root[tx], a * (float)mult);
                }
                __syncthreads();
            }
        }
    }

    // ===== last barrier: arrive (release); only blocks 0..2 wait =====
    __syncthreads();
    if (tx == 0) {
        if (atom_add_release_gpu(&g_bar_cnt, 1u) == (unsigned)(NB - 1)) {
            *(volatile unsigned*)&g_bar_cnt = 0u;
            st_release_gpu(&g_bar_gen, my_gen + 1u);
        } else if (bid < 3) {
            int spin = 0;
            while (ld_acquire_gpu(&g_bar_gen) == my_gen)
                if (++spin > 64) __nanosleep(32);
        }
        my_gen++;
    }
    __syncthreads();
    if (bid >= 3) return;

    // ===== epilogue: block 2 cleans S1 state; blocks 0/1 do heads =====
    if (bid == 2) {
        int n1v = g_n1; if (n1v > CAP1) n1v = CAP1;
        for (int i = tx; i < n1v; i += NT) {
            int s = g_s1_nodes[i];
            g_slot1[s] = 0;
            g_bm1[s >> 5] = 0u;
        }
        __syncthreads();
        if (tx == 0) { g_n1 = 0; g_ne1 = 0; g_ne2 = 0; }
        return;
    }

    // blocks 0 (actor) and 1 (critic): softmax(root) locally, then head
    {
        const int t = tx;
        if (t < H_DIM) sh_h[t] = g_root[t];
        __syncthreads();
        if (wid == 0) {
            float m = fmaxf(fmaxf(sh_h[lane], sh_h[lane + 32]),
                            fmaxf(sh_h[lane + 64], sh_h[lane + 96]));
            m = warp_max_f(m);
            if (lane == 0) s_mx = m;
        }
        __syncthreads();
        if (t < H_DIM) sh_h[t] = expf(sh_h[t] - s_mx);
        __syncthreads();
        if (wid == 0) {
            float sm = sh_h[lane] + sh_h[lane + 32] + sh_h[lane + 64] + sh_h[lane + 96];
            sm = warp_sum_f(sm);
            if (lane == 0) s_sum = sm;
        }
        __syncthreads();
        if (t < H_DIM) sh_h[t] *= (1.f / s_sum);
        __syncthreads();

        if (bid == 0) {
            if (t < LIN_DIM) {
                float a = a1_b[t];
#pragma unroll 8
                for (int k = 0; k < H_DIM; k++) a = fmaf(sh_h[k], a1_w[k * LIN_DIM + t], a);
                s_hid[t] = fmaxf(a, 0.f);
            }
            __syncthreads();
            if (t < LIN_DIM) {
                int q = t >> 7, j = t & 127;
                const int k0 = q * 128;
                float p = 0.f;
#pragma unroll 8
                for (int k = 0; k < 128; k++)
                    p = fmaf(s_hid[k0 + k], a2_w[(k0 + k) * H_DIM + j], p);
                sh_p[t] = p;
            }
            __syncthreads();
            if (t < H_DIM)
                out[t] = a2_b[t] + sh_p[t] + sh_p[t + 128] + sh_p[t + 256] + sh_p[t + 384];
        } else {
            if (t < LIN_DIM) {
                float a = c1_b[t];
#pragma unroll 8
                for (int k = 0; k < H_DIM; k++) a = fmaf(sh_h[k], c1_w[k * LIN_DIM + t], a);
                s_hid[t] = fmaxf(a, 0.f);
            }
            __syncthreads();
            if (t < LIN_DIM) {
                float p = warp_sum_f(s_hid[t] * c2_w[t]);
                if (lane == 0) sh_p[wid] = p;
            }
            __syncthreads();
            if (t == 0) {
                float a = c2_b[0];
#pragma unroll
                for (int i = 0; i < 16; i++) a += sh_p[i];
                if (out_size > H_DIM) out[H_DIM] = a;
            }
        }
    }
}

// ---------------- launch ----------------
extern "C" void kernel_launch(void* const* d_in, const int* in_sizes, int n_in,
                              void* d_out, int out_size) {
    const int*   cls  = (const int*)  d_in[0];
    const float* norm = (const float*)d_in[1];
    const int*   src  = (const int*)  d_in[2];
    const int*   dst  = (const int*)  d_in[3];
    const float* W0   = (const float*)d_in[4];
    const float* W1   = (const float*)d_in[5];
    const float* W2   = (const float*)d_in[6];
    const float* a1_w = (const float*)d_in[7];
    const float* a1_b = (const float*)d_in[8];
    const float* a2_w = (const float*)d_in[9];
    const float* a2_b = (const float*)d_in[10];
    const float* c1_w = (const float*)d_in[11];
    const float* c1_b = (const float*)d_in[12];
    const float* c2_w = (const float*)d_in[13];
    const float* c2_b = (const float*)d_in[14];
    float* out = (float*)d_out;

    k_fused<<<NB, NT>>>(cls, norm, src, dst, W0, W1, W2,
                        a1_w, a1_b, a2_w, a2_b, c1_w, c1_b, c2_w, c2_b,
                        out, out_size);
}

// round 16
// speedup vs baseline: 1.3563x; 1.0481x over previous
#include <cuda_runtime.h>
#include <math.h>
#include <stdint.h>

#define N_NODES 50000
#define N_EDGES 800000
#define NUM_RELS 16
#define H_DIM 128
#define LIN_DIM 512

#define CAP1 256
#define CAP2 2048
#define CAPE1 512
#define CAPE2 4096

#define BM_WORDS ((N_NODES + 31) / 32)   // 1563

#define NB 148                 // 1 block/SM
#define NT 1024                // 32 warps/SM
#define NQ (N_EDGES / 4)       // 200000 int4 quads
#define QPB ((NQ + NB - 1) / NB)     // 1352 quads per block
#define GRP (NT / H_DIM)       // 8 k-groups (P5 GEMV)
#define KS  (H_DIM / GRP)      // 16 k's per group
#define GRP2 4                 // 4 k-groups (P4 half-block GEMV, 512 thr)
#define KS2  (H_DIM / GRP2)    // 32 k's per group

// -------- scratch (device globals; zero-init valid; self-cleaning per launch) --------
__device__ int          g_slot1[N_NODES];       // 0 = absent, slot+1
__device__ int          g_slot2[N_NODES];       // 0 = absent, slot+1
__device__ unsigned int g_bm1[BM_WORDS + 1];
__device__ unsigned int g_bm2[BM_WORDS + 1];
__device__ int    g_n1, g_n2, g_ne1, g_ne2;
__device__ int    g_s1_nodes[CAP1];
__device__ int    g_s2_nodes[CAP2];
__device__ int    g_e1_src[CAPE1];
__device__ int    g_e2_src[CAPE2];
__device__ int    g_e2_dslot[CAPE2];
__device__ float  g_Ssm[CAP2 * NUM_RELS];       // per-(S2 slot, rel) sums (epilogue-cleaned)
__device__ float  g_h2[CAP1 * H_DIM];           // epilogue-cleaned (touched rows)
__device__ float  g_root[H_DIM];                // cleared in P1 (block 0)

// persistent-generation grid barrier
__device__ unsigned g_bar_cnt;
__device__ unsigned g_bar_gen;

__device__ __forceinline__ unsigned atom_add_release_gpu(unsigned* p, unsigned v) {
    unsigned old;
    asm volatile("atom.add.release.gpu.u32 %0, [%1], %2;"
                 : "=r"(old) : "l"(p), "r"(v) : "memory");
    return old;
}
__device__ __forceinline__ unsigned ld_acquire_gpu(unsigned* p) {
    unsigned v;
    asm volatile("ld.acquire.gpu.u32 %0, [%1];" : "=r"(v) : "l"(p) : "memory");
    return v;
}
__device__ __forceinline__ void st_release_gpu(unsigned* p, unsigned v) {
    asm volatile("st.release.gpu.u32 [%0], %1;" :: "l"(p), "r"(v) : "memory");
}

// ---- bulk-async copy helpers (UBLKCP on sm_103a) ----
__device__ __forceinline__ uint32_t smem_u32(const void* p) {
    uint32_t a;
    asm("{ .reg .u64 t; cvta.to.shared.u64 t, %1; cvt.u32.u64 %0, t; }"
        : "=r"(a) : "l"(p));
    return a;
}
__device__ __forceinline__ void mbar_init(uint32_t mb, uint32_t cnt) {
    asm volatile("mbarrier.init.shared.b64 [%0], %1;" :: "r"(mb), "r"(cnt) : "memory");
}
__device__ __forceinline__ void mbar_expect_tx(uint32_t mb, uint32_t bytes) {
    asm volatile("mbarrier.arrive.expect_tx.shared.b64 _, [%0], %1;"
                 :: "r"(mb), "r"(bytes) : "memory");
}
__device__ __forceinline__ void bulk_g2s(uint32_t smem, const void* gsrc,
                                         uint32_t bytes, uint32_t mb) {
    asm volatile("cp.async.bulk.shared::cta.global.mbarrier::complete_tx::bytes "
                 "[%0], [%1], %2, [%3];"
                 :: "r"(smem), "l"(gsrc), "r"(bytes), "r"(mb) : "memory");
}
__device__ __forceinline__ void mbar_wait0(uint32_t mb) {
    uint32_t done;
    asm volatile(
        "{\n\t.reg .pred p;\n\t"
        "mbarrier.try_wait.parity.acquire.cta.shared::cta.b64 p, [%1], 0;\n\t"
        "selp.b32 %0, 1, 0, p;\n\t}"
        : "=r"(done) : "r"(mb) : "memory");
    if (!done) {
        asm volatile(
            "{\n\t.reg .pred P1;\n\t"
            "WL_%=:\n\t"
            "mbarrier.try_wait.parity.acquire.cta.shared::cta.b64 P1, [%0], 0, 0x989680;\n\t"
            "@P1 bra.uni WD_%=;\n\t"
            "bra.uni WL_%=;\n\t"
            "WD_%=:\n\t}"
            :: "r"(mb) : "memory");
    }
}

#define GRID_SYNC()                                                          \
    do {                                                                     \
        __syncthreads();                                                     \
        if (threadIdx.x == 0) {                                              \
            if (atom_add_release_gpu(&g_bar_cnt, 1u) == (unsigned)(NB - 1)) {\
                *(volatile unsigned*)&g_bar_cnt = 0u;                        \
                st_release_gpu(&g_bar_gen, my_gen + 1u);                     \
            } else {                                                         \
                int spin = 0;                                                \
                while (ld_acquire_gpu(&g_bar_gen) == my_gen)                 \
                    if (++spin > 64) __nanosleep(32);                        \
            }                                                                \
            my_gen++;                                                        \
        }                                                                    \
        __syncthreads();                                                     \
    } while (0)

__device__ __forceinline__ float warp_max_f(float v) {
#pragma unroll
    for (int o = 16; o > 0; o >>= 1) v = fmaxf(v, __shfl_down_sync(0xffffffffu, v, o));
    return v;
}
__device__ __forceinline__ float warp_sum_f(float v) {
#pragma unroll
    for (int o = 16; o > 0; o >>= 1) v += __shfl_down_sync(0xffffffffu, v, o);
    return v;
}

__global__ void __launch_bounds__(NT, 1) k_fused(
    const int* __restrict__ cls, const float* __restrict__ norm,
    const int* __restrict__ src, const int* __restrict__ dst,
    const float* __restrict__ W0, const float* __restrict__ W1,
    const float* __restrict__ W2,
    const float* __restrict__ a1_w, const float* __restrict__ a1_b,
    const float* __restrict__ a2_w, const float* __restrict__ a2_b,
    const float* __restrict__ c1_w, const float* __restrict__ c1_b,
    const float* __restrict__ c2_w, const float* __restrict__ c2_b,
    float* __restrict__ out, int out_size)
{
    const int tx  = threadIdx.x;
    const int bid = blockIdx.x;
    const int wid  = tx >> 5;
    const int lane = tx & 31;

    const int q0     = bid * QPB;
    const int nq_blk = (NQ - q0 < QPB) ? (NQ - q0) : QPB;

    unsigned my_gen = 0;
    if (tx == 0) my_gen = ld_acquire_gpu(&g_bar_gen);

    __shared__ int4     sh_dst4[QPB + 1];          // 21.6 KB (TMA dest)
    __shared__ int4     sh_src4[QPB + 1];          // 21.6 KB (TMA dest)
    __shared__ unsigned sh_bm[BM_WORDS + 1];       // 6.3 KB (bm1 in P2, bm2 in P3)
    __shared__ float    sh_hh[2][H_DIM];
    __shared__ float    sh_h[H_DIM];
    __shared__ float    sh_p[NT];                  // 4 KB
    __shared__ float    s_hid[LIN_DIM];            // 2 KB
    __shared__ float    s_mx, s_sum;
    __shared__ uint64_t s_mbar;

    const uint32_t mb = smem_u32(&s_mbar);

    // ===== P1: bulk-copy slice -> SMEM; clear root; scan dst==0 -> S1/E1 =====
    {
        if (tx == 0) mbar_init(mb, 1);
        __syncthreads();
        if (tx == 0) {
            uint32_t bytes = (uint32_t)nq_blk * 16u;
            mbar_expect_tx(mb, 2u * bytes);
            bulk_g2s(smem_u32(sh_dst4), dst + 4 * q0, bytes, mb);
            bulk_g2s(smem_u32(sh_src4), src + 4 * q0, bytes, mb);
        }
        if (bid == 0 && tx < H_DIM) g_root[tx] = 0.f;

        mbar_wait0(mb);

#pragma unroll
        for (int half = 0; half < 2; half++) {
            int li = tx + half * NT;
            if (li < nq_blk) {
                const int4 d4 = sh_dst4[li];
                int dv[4] = {d4.x, d4.y, d4.z, d4.w};
#pragma unroll
                for (int k = 0; k < 4; k++) {
                    if (dv[k] == 0) {
                        const int* sp = reinterpret_cast<const int*>(&sh_src4[li]);
                        int s = sp[k];
                        int p = atomicAdd(&g_ne1, 1);
                        if (p < CAPE1) g_e1_src[p] = s;
                        if (atomicCAS(&g_slot1[s], 0, -1) == 0) {
                            int sl = atomicAdd(&g_n1, 1);
                            if (sl < CAP1) g_s1_nodes[sl] = s;
                            g_slot1[s] = sl + 1;
                            atomicOr(&g_bm1[s >> 5], 1u << (s & 31));
                        }
                    }
                }
            }
        }
    }
    GRID_SYNC();   // barrier 1

    // ===== P2: SMEM re-scan (bm1): dst in S1 -> E2 list + register src into S2 =====
    {
        for (int i = tx; i <= BM_WORDS; i += NT) sh_bm[i] = g_bm1[i];
        __syncthreads();
#pragma unroll
        for (int half = 0; half < 2; half++) {
            int li = tx + half * NT;
            if (li < nq_blk) {
                const int4 d4 = sh_dst4[li];
                int dv[4] = {d4.x, d4.y, d4.z, d4.w};
#pragma unroll
                for (int k = 0; k < 4; k++) {
                    int d = dv[k];
                    if (sh_bm[d >> 5] & (1u << (d & 31))) {
                        int sl = g_slot1[d] - 1;
                        if (sl >= 0 && sl < CAP1) {
                            const int* sp = reinterpret_cast<const int*>(&sh_src4[li]);
                            int s = sp[k];
                            int p = atomicAdd(&g_ne2, 1);
                            if (p < CAPE2) { g_e2_src[p] = s; g_e2_dslot[p] = sl; }
                            if (atomicCAS(&g_slot2[s], 0, -1) == 0) {
                                int q = atomicAdd(&g_n2, 1);
                                if (q < CAP2) g_s2_nodes[q] = s;
                                g_slot2[s] = q + 1;
                                atomicOr(&g_bm2[s >> 5], 1u << (s & 31));
                            }
                        }
                    }
                }
            }
        }
    }
    GRID_SYNC();   // barrier 2

    // ===== P3: SMEM re-scan (bm2): dst in S2 -> Ssm[slot2[d]][cls[s]] += norm[s] =====
    {
        for (int i = tx; i <= BM_WORDS; i += NT) sh_bm[i] = g_bm2[i];
        __syncthreads();
#pragma unroll
        for (int half = 0; half < 2; half++) {
            int li = tx + half * NT;
            if (li < nq_blk) {
                const int4 d4 = sh_dst4[li];
                int dv[4] = {d4.x, d4.y, d4.z, d4.w};
#pragma unroll
                for (int k = 0; k < 4; k++) {
                    int d = dv[k];
                    if (sh_bm[d >> 5] & (1u << (d & 31))) {
                        int sl = g_slot2[d] - 1;
                        if (sl >= 0 && sl < CAP2) {
                            const int* sp = reinterpret_cast<const int*>(&sh_src4[li]);
                            int s = sp[k];
                            atomicAdd(&g_Ssm[sl * NUM_RELS + cls[s]], norm[s]);
                        }
                    }
                }
            }
        }
    }
    GRID_SYNC();   // barrier 3

    // ===== P4: two half-block (512-thr) GEMVs per block, one E2 edge each =====
    // msg1 = (relu(Ssm[slot2[s]] . T0) @ W1[cls[s]]) * norm[s] -> h2[dslot]
    {
        int ne2 = *(volatile int*)&g_ne2; if (ne2 > CAPE2) ne2 = CAPE2;
        const int grp = tx >> 9;
        const int gtx = tx & 511;
        const int j = gtx & (H_DIM - 1), q = gtx >> 7;
        const int trips = (ne2 + 2 * NB - 1) / (2 * NB);
        for (int t = 0; t < trips; t++) {
            int e = t * 2 * NB + bid * 2 + grp;
            bool act = (e < ne2);
            int s = 0, dsl = -1, ssl = -1, c = 0;
            float nm = 0.f;
            if (act) {
                s   = g_e2_src[e];
                dsl = g_e2_dslot[e];
                ssl = g_slot2[s] - 1;
                c   = cls[s];
                nm  = norm[s];
                act = (ssl >= 0 && ssl < CAP2);
                if (act && gtx < H_DIM) {
                    const float* Sv = &g_Ssm[ssl * NUM_RELS];
                    float h = 0.f;
#pragma unroll
                    for (int r = 0; r < NUM_RELS; r++)
                        h = fmaf(Sv[r], W0[(r * NUM_RELS + r) * H_DIM + gtx], h);
                    sh_hh[grp][gtx] = fmaxf(h, 0.f);
                }
            }
            __syncthreads();
            if (act) {
                const float* Wc = W1 + c * H_DIM * H_DIM;
                float p = 0.f;
#pragma unroll
                for (int kk = 0; kk < KS2; kk++) {
                    int k = q * KS2 + kk;
                    p = fmaf(sh_hh[grp][k], Wc[k * H_DIM + j], p);
                }
                sh_p[tx] = p;
            }
            __syncthreads();
            if (act && gtx < H_DIM && dsl >= 0 && dsl < CAP1) {
                float a = 0.f;
#pragma unroll
                for (int g = 0; g < GRP2; g++) a += sh_p[grp * 512 + gtx + g * H_DIM];
                atomicAdd(&g_h2[dsl * H_DIM + gtx], a * nm);
            }
            __syncthreads();
        }
    }
    GRID_SYNC();   // barrier 4

    // ===== P5: block-wide msg2 per S1 node + root accumulation =====
    {
        int n1v = *(volatile int*)&g_n1; if (n1v > CAP1)  n1v = CAP1;
        int ne1 = *(volatile int*)&g_ne1; if (ne1 > CAPE1) ne1 = CAPE1;
        if (bid < n1v) {
            const int j = tx & (H_DIM - 1), q = tx >> 7;
            for (int sl = bid; sl < n1v; sl += NB) {
                if (tx < H_DIM) sh_h[tx] = fmaxf(g_h2[sl * H_DIM + tx], 0.f);
                __syncthreads();
                int node = g_s1_nodes[sl];
                int c = cls[node];
                float nm = norm[node];
                const float* Wc = W2 + c * H_DIM * H_DIM;
                float p = 0.f;
#pragma unroll
                for (int kk = 0; kk < KS; kk++) {
                    int k = q * KS + kk;
                    p = fmaf(sh_h[k], Wc[k * H_DIM + j], p);
                }
                sh_p[tx] = p;
                __syncthreads();
                if (tx < H_DIM) {
                    float a = 0.f;
#pragma unroll
                    for (int g = 0; g < GRP; g++) a += sh_p[tx + g * H_DIM];
                    a *= nm;
                    int mult = 0;
                    for (int i = 0; i < ne1; i++) mult += (g_e1_src[i] == node);
                    if (mult > 0) atomicAdd(&g_root[tx], a * (float)mult);
                }
                __syncthreads();
            }
        }
    }

    // ===== last barrier: arrive (release); only blocks 0..3 wait =====
    __syncthreads();
    if (tx == 0) {
        if (atom_add_release_gpu(&g_bar_cnt, 1u) == (unsigned)(NB - 1)) {
            *(volatile unsigned*)&g_bar_cnt = 0u;
            st_release_gpu(&g_bar_gen, my_gen + 1u);
        } else if (bid < 4) {
            int spin = 0;
            while (ld_acquire_gpu(&g_bar_gen) == my_gen)
                if (++spin > 64) __nanosleep(32);
        }
        my_gen++;
    }
    __syncthreads();
    if (bid >= 4) return;

    // ===== epilogue: 2 cleans S1; 3 cleans S2 + Ssm + h2; 0/1 heads =====
    if (bid == 2) {
        int n1v = g_n1; if (n1v > CAP1) n1v = CAP1;
        for (int i = tx; i < n1v; i += NT) {
            int s = g_s1_nodes[i];
            g_slot1[s] = 0;
            g_bm1[s >> 5] = 0u;
        }
        __syncthreads();
        if (tx == 0) { g_n1 = 0; g_ne1 = 0; }
        return;
    }
    if (bid == 3) {
        int n1v = g_n1; if (n1v > CAP1) n1v = CAP1;
        int n2v = g_n2; if (n2v > CAP2) n2v = CAP2;
        for (int i = tx; i < n2v; i += NT) {
            int s = g_s2_nodes[i];
            g_slot2[s] = 0;
            g_bm2[s >> 5] = 0u;
        }
        for (int i = tx; i < n2v * NUM_RELS; i += NT) g_Ssm[i] = 0.f;
        for (int i = tx; i < n1v * H_DIM; i += NT) g_h2[i] = 0.f;
        __syncthreads();
        if (tx == 0) { g_n2 = 0; g_ne2 = 0; }
        return;
    }

    // blocks 0 (actor) and 1 (critic): softmax(root) locally, then head
    {
        const int t = tx;
        if (t < H_DIM) sh_h[t] = g_root[t];
        __syncthreads();
        if (wid == 0) {
            float m = fmaxf(fmaxf(sh_h[lane], sh_h[lane + 32]),
                            fmaxf(sh_h[lane + 64], sh_h[lane + 96]));
            m = warp_max_f(m);
            if (lane == 0) s_mx = m;
        }
        __syncthreads();
        if (t < H_DIM) sh_h[t] = expf(sh_h[t] - s_mx);
        __syncthreads();
        if (wid == 0) {
            float sm = sh_h[lane] + sh_h[lane + 32] + sh_h[lane + 64] + sh_h[lane + 96];
            sm = warp_sum_f(sm);
            if (lane == 0) s_sum = sm;
        }
        __syncthreads();
        if (t < H_DIM) sh_h[t] *= (1.f / s_sum);
        __syncthreads();

        if (bid == 0) {
            if (t < LIN_DIM) {
                float a = a1_b[t];
#pragma unroll 8
                for (int k = 0; k < H_DIM; k++) a = fmaf(sh_h[k], a1_w[k * LIN_DIM + t], a);
                s_hid[t] = fmaxf(a, 0.f);
            }
            __syncthreads();
            if (t < LIN_DIM) {
                int q = t >> 7, j = t & 127;
                const int k0 = q * 128;
                float p = 0.f;
#pragma unroll 8
                for (int k = 0; k < 128; k++)
                    p = fmaf(s_hid[k0 + k], a2_w[(k0 + k) * H_DIM + j], p);
                sh_p[t] = p;
            }
            __syncthreads();
            if (t < H_DIM)
                out[t] = a2_b[t] + sh_p[t] + sh_p[t + 128] + sh_p[t + 256] + sh_p[t + 384];
        } else {
            if (t < LIN_DIM) {
                float a = c1_b[t];
#pragma unroll 8
                for (int k = 0; k < H_DIM; k++) a = fmaf(sh_h[k], c1_w[k * LIN_DIM + t], a);
                s_hid[t] = fmaxf(a, 0.f);
            }
            __syncthreads();
            if (t < LIN_DIM) {
                float p = warp_sum_f(s_hid[t] * c2_w[t]);
                if (lane == 0) sh_p[wid] = p;
            }
            __syncthreads();
            if (t == 0) {
                float a = c2_b[0];
#pragma unroll
                for (int i = 0; i < 16; i++) a += sh_p[i];
                if (out_size > H_DIM) out[H_DIM] = a;
            }
        }
    }
}

// ---------------- launch ----------------
extern "C" void kernel_launch(void* const* d_in, const int* in_sizes, int n_in,
                              void* d_out, int out_size) {
    const int*   cls  = (const int*)  d_in[0];
    const float* norm = (const float*)d_in[1];
    const int*   src  = (const int*)  d_in[2];
    const int*   dst  = (const int*)  d_in[3];
    const float* W0   = (const float*)d_in[4];
    const float* W1   = (const float*)d_in[5];
    const float* W2   = (const float*)d_in[6];
    const float* a1_w = (const float*)d_in[7];
    const float* a1_b = (const float*)d_in[8];
    const float* a2_w = (const float*)d_in[9];
    const float* a2_b = (const float*)d_in[10];
    const float* c1_w = (const float*)d_in[11];
    const float* c1_b = (const float*)d_in[12];
    const float* c2_w = (const float*)d_in[13];
    const float* c2_b = (const float*)d_in[14];
    float* out = (float*)d_out;

    k_fused<<<NB, NT>>>(cls, norm, src, dst, W0, W1, W2,
                        a1_w, a1_b, a2_w, a2_b, c1_w, c1_b, c2_w, c2_b,
                        out, out_size);
}

// round 17
// speedup vs baseline: 1.4288x; 1.0535x over previous
#include <cuda_runtime.h>
#include <math.h>
#include <stdint.h>

#define N_NODES 50000
#define N_EDGES 800000
#define NUM_RELS 16
#define H_DIM 128
#define LIN_DIM 512

#define CAP1 256
#define CAP2 2048
#define CAPE1 512
#define CAPE2 4096

#define BM_WORDS ((N_NODES + 31) / 32)   // 1563

#define NB 148                 // 1 block/SM
#define NT 1024                // 32 warps/SM
#define NQ (N_EDGES / 4)       // 200000 int4 quads
#define QPB ((NQ + NB - 1) / NB)     // 1352 quads per block
#define GRP (NT / H_DIM)       // 8 k-groups (P5 GEMV)
#define KS  (H_DIM / GRP)      // 16 k's per group
#define GRP2 4                 // 4 k-groups (P4 half-block GEMV, 512 thr)
#define KS2  (H_DIM / GRP2)    // 32 k's per group

// -------- scratch (device globals; zero-init valid; self-cleaning per launch) --------
__device__ int          g_slot1[N_NODES];       // 0 = absent, slot+1
__device__ int          g_slot2[N_NODES];       // 0 = absent, slot+1
__device__ unsigned int g_bm1[BM_WORDS + 1];
__device__ unsigned int g_bm2[BM_WORDS + 1];
__device__ int    g_n1, g_n2, g_ne1, g_ne2;
__device__ int    g_s1_nodes[CAP1];
__device__ int    g_s2_nodes[CAP2];
__device__ int    g_e1_src[CAPE1];
__device__ int    g_e2_src[CAPE2];
__device__ int    g_e2_dslot[CAPE2];
__device__ float  g_Ssm[CAP2 * NUM_RELS];       // per-(S2 slot, rel) sums (epilogue-cleaned)
__device__ float  g_h2[CAP1 * H_DIM];           // epilogue-cleaned (touched rows)
__device__ float  g_root[H_DIM];                // cleared in P1 (block 0)

// persistent-generation grid barrier
__device__ unsigned g_bar_cnt;
__device__ unsigned g_bar_gen;

__device__ __forceinline__ unsigned atom_add_release_gpu(unsigned* p, unsigned v) {
    unsigned old;
    asm volatile("atom.add.release.gpu.u32 %0, [%1], %2;"
                 : "=r"(old) : "l"(p), "r"(v) : "memory");
    return old;
}
__device__ __forceinline__ unsigned ld_acquire_gpu(unsigned* p) {
    unsigned v;
    asm volatile("ld.acquire.gpu.u32 %0, [%1];" : "=r"(v) : "l"(p) : "memory");
    return v;
}
__device__ __forceinline__ void st_release_gpu(unsigned* p, unsigned v) {
    asm volatile("st.release.gpu.u32 [%0], %1;" :: "l"(p), "r"(v) : "memory");
}

// ---- bulk-async copy helpers (UBLKCP on sm_103a) ----
__device__ __forceinline__ uint32_t smem_u32(const void* p) {
    uint32_t a;
    asm("{ .reg .u64 t; cvta.to.shared.u64 t, %1; cvt.u32.u64 %0, t; }"
        : "=r"(a) : "l"(p));
    return a;
}
__device__ __forceinline__ void mbar_init(uint32_t mb, uint32_t cnt) {
    asm volatile("mbarrier.init.shared.b64 [%0], %1;" :: "r"(mb), "r"(cnt) : "memory");
}
__device__ __forceinline__ void mbar_expect_tx(uint32_t mb, uint32_t bytes) {
    asm volatile("mbarrier.arrive.expect_tx.shared.b64 _, [%0], %1;"
                 :: "r"(mb), "r"(bytes) : "memory");
}
__device__ __forceinline__ void bulk_g2s(uint32_t smem, const void* gsrc,
                                         uint32_t bytes, uint32_t mb) {
    asm volatile("cp.async.bulk.shared::cta.global.mbarrier::complete_tx::bytes "
                 "[%0], [%1], %2, [%3];"
                 :: "r"(smem), "l"(gsrc), "r"(bytes), "r"(mb) : "memory");
}
__device__ __forceinline__ void mbar_wait0(uint32_t mb) {
    uint32_t done;
    asm volatile(
        "{\n\t.reg .pred p;\n\t"
        "mbarrier.try_wait.parity.acquire.cta.shared::cta.b64 p, [%1], 0;\n\t"
        "selp.b32 %0, 1, 0, p;\n\t}"
        : "=r"(done) : "r"(mb) : "memory");
    if (!done) {
        asm volatile(
            "{\n\t.reg .pred P1;\n\t"
            "WL_%=:\n\t"
            "mbarrier.try_wait.parity.acquire.cta.shared::cta.b64 P1, [%0], 0, 0x989680;\n\t"
            "@P1 bra.uni WD_%=;\n\t"
            "bra.uni WL_%=;\n\t"
            "WD_%=:\n\t}"
            :: "r"(mb) : "memory");
    }
}

#define GRID_SYNC()                                                          \
    do {                                                                     \
        __syncthreads();                                                     \
        if (threadIdx.x == 0) {                                              \
            if (atom_add_release_gpu(&g_bar_cnt, 1u) == (unsigned)(NB - 1)) {\
                *(volatile unsigned*)&g_bar_cnt = 0u;                        \
                st_release_gpu(&g_bar_gen, my_gen + 1u);                     \
            } else {                                                         \
                int spin = 0;                                                \
                while (ld_acquire_gpu(&g_bar_gen) == my_gen)                 \
                    if (++spin > 64) __nanosleep(32);                        \
            }                                                                \
            my_gen++;                                                        \
        }                                                                    \
        __syncthreads();                                                     \
    } while (0)

__device__ __forceinline__ float warp_max_f(float v) {
#pragma unroll
    for (int o = 16; o > 0; o >>= 1) v = fmaxf(v, __shfl_down_sync(0xffffffffu, v, o));
    return v;
}
__device__ __forceinline__ float warp_sum_f(float v) {
#pragma unroll
    for (int o = 16; o > 0; o >>= 1) v += __shfl_down_sync(0xffffffffu, v, o);
    return v;
}

__global__ void __launch_bounds__(NT, 1) k_fused(
    const int* __restrict__ cls, const float* __restrict__ norm,
    const int* __restrict__ src, const int* __restrict__ dst,
    const float* __restrict__ W0, const float* __restrict__ W1,
    const float* __restrict__ W2,
    const float* __restrict__ a1_w, const float* __restrict__ a1_b,
    const float* __restrict__ a2_w, const float* __restrict__ a2_b,
    const float* __restrict__ c1_w, const float* __restrict__ c1_b,
    const float* __restrict__ c2_w, const float* __restrict__ c2_b,
    float* __restrict__ out, int out_size)
{
    const int tx  = threadIdx.x;
    const int bid = blockIdx.x;
    const int wid  = tx >> 5;
    const int lane = tx & 31;

    const int q0     = bid * QPB;
    const int nq_blk = (NQ - q0 < QPB) ? (NQ - q0) : QPB;

    unsigned my_gen = 0;
    if (tx == 0) my_gen = ld_acquire_gpu(&g_bar_gen);

    __shared__ int4     sh_dst4[QPB + 1];          // 21.6 KB (TMA dest)
    __shared__ int4     sh_src4[QPB + 1];          // 21.6 KB (TMA dest)
    __shared__ unsigned sh_bm[BM_WORDS + 1];       // 6.3 KB (bm1 in P2, bm2 in P3)
    __shared__ int      sh_e1[CAPE1];              // 2 KB (P5)
    __shared__ float    sh_hh[2][H_DIM];
    __shared__ float    sh_h[H_DIM];
    __shared__ float    sh_p[NT];                  // 4 KB
    __shared__ float    s_hid[LIN_DIM];            // 2 KB
    __shared__ float    s_mx, s_sum;
    __shared__ uint64_t s_mbar;

    const uint32_t mb = smem_u32(&s_mbar);

    // ===== P1: bulk-copy slice -> SMEM; clear root; scan dst==0 -> S1/E1 =====
    {
        if (tx == 0) mbar_init(mb, 1);
        __syncthreads();
        if (tx == 0) {
            uint32_t bytes = (uint32_t)nq_blk * 16u;
            mbar_expect_tx(mb, 2u * bytes);
            bulk_g2s(smem_u32(sh_dst4), dst + 4 * q0, bytes, mb);
            bulk_g2s(smem_u32(sh_src4), src + 4 * q0, bytes, mb);
        }
        if (bid == 0 && tx < H_DIM) g_root[tx] = 0.f;

        mbar_wait0(mb);

#pragma unroll
        for (int half = 0; half < 2; half++) {
            int li = tx + half * NT;
            if (li < nq_blk) {
                const int4 d4 = sh_dst4[li];
                int dv[4] = {d4.x, d4.y, d4.z, d4.w};
#pragma unroll
                for (int k = 0; k < 4; k++) {
                    if (dv[k] == 0) {
                        const int* sp = reinterpret_cast<const int*>(&sh_src4[li]);
                        int s = sp[k];
                        int p = atomicAdd(&g_ne1, 1);
                        if (p < CAPE1) g_e1_src[p] = s;
                        if (atomicCAS(&g_slot1[s], 0, -1) == 0) {
                            int sl = atomicAdd(&g_n1, 1);
                            if (sl < CAP1) g_s1_nodes[sl] = s;
                            g_slot1[s] = sl + 1;
                            atomicOr(&g_bm1[s >> 5], 1u << (s & 31));
                        }
                    }
                }
            }
        }
    }
    GRID_SYNC();   // barrier 1

    // ===== P2: SMEM re-scan (bm1): dst in S1 -> E2 list + register src into S2 =====
    {
        for (int i = tx; i <= BM_WORDS; i += NT) sh_bm[i] = g_bm1[i];
        __syncthreads();
#pragma unroll
        for (int half = 0; half < 2; half++) {
            int li = tx + half * NT;
            if (li < nq_blk) {
                const int4 d4 = sh_dst4[li];
                int dv[4] = {d4.x, d4.y, d4.z, d4.w};
#pragma unroll
                for (int k = 0; k < 4; k++) {
                    int d = dv[k];
                    if (sh_bm[d >> 5] & (1u << (d & 31))) {
                        int sl = g_slot1[d] - 1;
                        if (sl >= 0 && sl < CAP1) {
                            const int* sp = reinterpret_cast<const int*>(&sh_src4[li]);
                            int s = sp[k];
                            int p = atomicAdd(&g_ne2, 1);
                            if (p < CAPE2) { g_e2_src[p] = s; g_e2_dslot[p] = sl; }
                            if (atomicCAS(&g_slot2[s], 0, -1) == 0) {
                                int q = atomicAdd(&g_n2, 1);
                                if (q < CAP2) g_s2_nodes[q] = s;
                                g_slot2[s] = q + 1;
                                atomicOr(&g_bm2[s >> 5], 1u << (s & 31));
                            }
                        }
                    }
                }
            }
        }
    }
    GRID_SYNC();   // barrier 2

    // ===== P3: SMEM re-scan (bm2): dst in S2 -> Ssm[slot2[d]][cls[s]] += norm[s] =====
    {
        for (int i = tx; i <= BM_WORDS; i += NT) sh_bm[i] = g_bm2[i];
        __syncthreads();
#pragma unroll
        for (int half = 0; half < 2; half++) {
            int li = tx + half * NT;
            if (li < nq_blk) {
                const int4 d4 = sh_dst4[li];
                int dv[4] = {d4.x, d4.y, d4.z, d4.w};
#pragma unroll
                for (int k = 0; k < 4; k++) {
                    int d = dv[k];
                    if (sh_bm[d >> 5] & (1u << (d & 31))) {
                        int sl = g_slot2[d] - 1;
                        if (sl >= 0 && sl < CAP2) {
                            const int* sp = reinterpret_cast<const int*>(&sh_src4[li]);
                            int s = sp[k];
                            atomicAdd(&g_Ssm[sl * NUM_RELS + cls[s]], norm[s]);
                        }
                    }
                }
            }
        }
    }
    GRID_SYNC();   // barrier 3

    // ===== P4: two half-block (512-thr) GEMVs per block, one E2 edge each =====
    // msg1 = (relu(Ssm[slot2[s]] . T0) @ W1[cls[s]]) * norm[s] -> h2[dslot]
    {
        int ne2 = *(volatile int*)&g_ne2; if (ne2 > CAPE2) ne2 = CAPE2;
        const int grp = tx >> 9;
        const int gtx = tx & 511;
        const int j = gtx & (H_DIM - 1), q = gtx >> 7;
        const int trips = (ne2 + 2 * NB - 1) / (2 * NB);
        for (int t = 0; t < trips; t++) {
            int e = t * 2 * NB + bid * 2 + grp;
            bool act = (e < ne2);
            int s = 0, dsl = -1, ssl = -1, c = 0;
            float nm = 0.f;
            if (act) {
                s   = g_e2_src[e];
                dsl = g_e2_dslot[e];
                ssl = g_slot2[s] - 1;
                c   = cls[s];
                nm  = norm[s];
                act = (ssl >= 0 && ssl < CAP2);
                if (act && gtx < H_DIM) {
                    const float* Sv = &g_Ssm[ssl * NUM_RELS];
                    float h = 0.f;
#pragma unroll
                    for (int r = 0; r < NUM_RELS; r++)
                        h = fmaf(Sv[r], W0[(r * NUM_RELS + r) * H_DIM + gtx], h);
                    sh_hh[grp][gtx] = fmaxf(h, 0.f);
                }
            }
            __syncthreads();
            if (act) {
                const float* Wc = W1 + c * H_DIM * H_DIM;
                float p = 0.f;
#pragma unroll
                for (int kk = 0; kk < KS2; kk++) {
                    int k = q * KS2 + kk;
                    p = fmaf(sh_hh[grp][k], Wc[k * H_DIM + j], p);
                }
                sh_p[tx] = p;
            }
            __syncthreads();
            if (act && gtx < H_DIM && dsl >= 0 && dsl < CAP1) {
                float a = 0.f;
#pragma unroll
                for (int g = 0; g < GRP2; g++) a += sh_p[grp * 512 + gtx + g * H_DIM];
                atomicAdd(&g_h2[dsl * H_DIM + gtx], a * nm);
            }
            __syncthreads();
        }
    }
    GRID_SYNC();   // barrier 4

    // ===== P5: block-wide msg2 per S1 node + root accumulation =====
    {
        int n1v = *(volatile int*)&g_n1; if (n1v > CAP1)  n1v = CAP1;
        int ne1 = *(volatile int*)&g_ne1; if (ne1 > CAPE1) ne1 = CAPE1;
        if (bid < n1v) {
            for (int i = tx; i < ne1; i += NT) sh_e1[i] = g_e1_src[i];
            __syncthreads();
            const int j = tx & (H_DIM - 1), q = tx >> 7;
            for (int sl = bid; sl < n1v; sl += NB) {
                if (tx < H_DIM) sh_h[tx] = fmaxf(g_h2[sl * H_DIM + tx], 0.f);
                __syncthreads();
                int node = g_s1_nodes[sl];
                int c = cls[node];
                float nm = norm[node];
                const float* Wc = W2 + c * H_DIM * H_DIM;
                float p = 0.f;
#pragma unroll
                for (int kk = 0; kk < KS; kk++) {
                    int k = q * KS + kk;
                    p = fmaf(sh_h[k], Wc[k * H_DIM + j], p);
                }
                sh_p[tx] = p;
                __syncthreads();
                if (tx < H_DIM) {
                    float a = 0.f;
#pragma unroll
                    for (int g = 0; g < GRP; g++) a += sh_p[tx + g * H_DIM];
                    a *= nm;
                    int mult = 0;
                    for (int i = 0; i < ne1; i++) mult += (sh_e1[i] == node);
                    if (mult > 0) atomicAdd(&g_root[tx], a * (float)mult);
                }
                __syncthreads();
            }
        }
    }

    // ===== last barrier: arrive (release); only blocks 0..3 wait =====
    __syncthreads();
    if (tx == 0) {
        if (atom_add_release_gpu(&g_bar_cnt, 1u) == (unsigned)(NB - 1)) {
            *(volatile unsigned*)&g_bar_cnt = 0u;
            st_release_gpu(&g_bar_gen, my_gen + 1u);
        } else if (bid < 4) {
            int spin = 0;
            while (ld_acquire_gpu(&g_bar_gen) == my_gen)
                if (++spin > 64) __nanosleep(32);
        }
        my_gen++;
    }
    __syncthreads();
    if (bid >= 4) return;

    // ===== epilogue: 2 cleans S1; 3 cleans S2 + Ssm + h2; 0/1 heads =====
    if (bid == 2) {
        int n1v = g_n1; if (n1v > CAP1) n1v = CAP1;
        for (int i = tx; i < n1v; i += NT) {
            int s = g_s1_nodes[i];
            g_slot1[s] = 0;
            g_bm1[s >> 5] = 0u;
        }
        __syncthreads();
        if (tx == 0) { g_n1 = 0; g_ne1 = 0; }
        return;
    }
    if (bid == 3) {
        int n1v = g_n1; if (n1v > CAP1) n1v = CAP1;
        int n2v = g_n2; if (n2v > CAP2) n2v = CAP2;
        for (int i = tx; i < n2v; i += NT) {
            int s = g_s2_nodes[i];
            g_slot2[s] = 0;
            g_bm2[s >> 5] = 0u;
        }
        for (int i = tx; i < n2v * NUM_RELS; i += NT) g_Ssm[i] = 0.f;
        for (int i = tx; i < n1v * H_DIM; i += NT) g_h2[i] = 0.f;
        __syncthreads();
        if (tx == 0) { g_n2 = 0; g_ne2 = 0; }
        return;
    }

    // blocks 0 (actor) and 1 (critic): softmax(root), then head — ALL 1024 threads
    {
        const int t = tx;
        if (t < H_DIM) sh_h[t] = g_root[t];
        __syncthreads();
        if (wid == 0) {
            float m = fmaxf(fmaxf(sh_h[lane], sh_h[lane + 32]),
                            fmaxf(sh_h[lane + 64], sh_h[lane + 96]));
            m = warp_max_f(m);
            if (lane == 0) s_mx = m;
        }
        __syncthreads();
        if (t < H_DIM) sh_h[t] = expf(sh_h[t] - s_mx);
        __syncthreads();
        if (wid == 0) {
            float sm = sh_h[lane] + sh_h[lane + 32] + sh_h[lane + 64] + sh_h[lane + 96];
            sm = warp_sum_f(sm);
            if (lane == 0) s_sum = sm;
        }
        __syncthreads();
        if (t < H_DIM) sh_h[t] *= (1.f / s_sum);
        __syncthreads();

        const float* w1 = (bid == 0) ? a1_w : c1_w;
        const float* b1 = (bid == 0) ? a1_b : c1_b;

        // layer 1: 128 -> 512 relu, 2-way k-split over 1024 threads
        {
            int u  = t & 511;
            int kh = t >> 9;              // 0 or 1
            const int k0 = kh * 64;
            float p = 0.f;
#pragma unroll 8
            for (int k = 0; k < 64; k++)
                p = fmaf(sh_h[k0 + k], w1[(k0 + k) * LIN_DIM + u], p);
            sh_p[t] = p;
        }
        __syncthreads();
        if (t < LIN_DIM)
            s_hid[t] = fmaxf(b1[t] + sh_p[t] + sh_p[t + 512], 0.f);
        __syncthreads();

        if (bid == 0) {
            // actor layer 2: 512 -> 128, 8-way k-split over 1024 threads
            {
                int u = t & 127;
                int q = t >> 7;           // 0..7
                const int k0 = q * 64;
                float p = 0.f;
#pragma unroll 8
                for (int k = 0; k < 64; k++)
                    p = fmaf(s_hid[k0 + k], a2_w[(k0 + k) * H_DIM + u], p);
                sh_p[t] = p;
            }
            __syncthreads();
            if (t < H_DIM) {
                float a = a2_b[t];
#pragma unroll
                for (int g = 0; g < 8; g++) a += sh_p[t + g * H_DIM];
                out[t] = a;
            }
        } else {
            // critic layer 2: 512 -> 1, warp-reduced over first 512 threads
            if (t < LIN_DIM) {
                float p = warp_sum_f(s_hid[t] * c2_w[t]);
                if (lane == 0) sh_p[wid] = p;
            }
            __syncthreads();
            if (t == 0) {
                float a = c2_b[0];
#pragma unroll
                for (int i = 0; i < 16; i++) a += sh_p[i];
                if (out_size > H_DIM) out[H_DIM] = a;
            }
        }
    }
}

// ---------------- launch ----------------
extern "C" void kernel_launch(void* const* d_in, const int* in_sizes, int n_in,
                              void* d_out, int out_size) {
    const int*   cls  = (const int*)  d_in[0];
    const float* norm = (const float*)d_in[1];
    const int*   src  = (const int*)  d_in[2];
    const int*   dst  = (const int*)  d_in[3];
    const float* W0   = (const float*)d_in[4];
    const float* W1   = (const float*)d_in[5];
    const float* W2   = (const float*)d_in[6];
    const float* a1_w = (const float*)d_in[7];
    const float* a1_b = (const float*)d_in[8];
    const float* a2_w = (const float*)d_in[9];
    const float* a2_b = (const float*)d_in[10];
    const float* c1_w = (const float*)d_in[11];
    const float* c1_b = (const float*)d_in[12];
    const float* c2_w = (const float*)d_in[13];
    const float* c2_b = (const float*)d_in[14];
    float* out = (float*)d_out;

    k_fused<<<NB, NT>>>(cls, norm, src, dst, W0, W1, W2,
                        a1_w, a1_b, a2_w, a2_b, c1_w, c1_b, c2_w, c2_b,
                        out, out_size);
}